// round 5
// baseline (speedup 1.0000x reference)
#include <cuda_runtime.h>
#include <cstdint>

// Problem shape (fixed by reference)
constexpr int B = 16, N = 8, M = 1024, F = 512;
constexpr int F4 = F / 4;              // 128 float4 columns
constexpr int M_CHUNK = 16;            // m-rows per tile
constexpr int M_CHUNKS = M / M_CHUNK;  // 64
constexpr int N_TILES = B * N * M_CHUNKS;  // 8192
constexpr int GRID = 148 * 8;          // persistent: 8 CTAs per SM, 1 wave
constexpr float LOG2E = 1.4426950408889634f;

__device__ __forceinline__ float ex2_approx(float x) {
    float r;
    asm("ex2.approx.f32 %0, %1;" : "=f"(r) : "f"(x));
    return r;
}
__device__ __forceinline__ float rcp_approx(float x) {
    float r;
    asm("rcp.approx.f32 %0, %1;" : "=f"(r) : "f"(x));
    return r;
}

// ---------------------------------------------------------------------------
// Persistent grid-stride kernel: GRID=1184 CTAs (8/SM, exactly one wave),
// each CTA loops over ~7 tiles (tile = (b,n,mc); 16 m-rows x 512 f).
// Removes the ~6 wave transitions + per-tile CTA exit/relaunch pipeline
// drains of the 8192-block version; prologue (mask-width detect) runs once
// per CTA instead of once per tile.
//
// Mask dtype detection: values in [0,13) => int64 (LE) has every odd 32-bit
// word == 0; OR over 256 odd words is nonzero for int32 w.p. 1-(1/13)^256.
//
// tanh(x) = 1 - 2/(exp(2x)+1)  ->  out = p - q * rcp(ex2(z*c1 + c0) + 1)
//   c1 = 2*e3*log2e, c0 = -2*e2*e3*log2e, p = e0+e1, q = 2*e1
// ---------------------------------------------------------------------------
__global__ __launch_bounds__(F4, 8)
void tanh_rt_kernel(const float4* __restrict__ z,
                    const int* __restrict__ mask32,
                    const float4* __restrict__ eta,   // [13] of (e0,e1,e2,e3)
                    float4* __restrict__ out) {
    const int f4 = threadIdx.x;            // 0..127

    // --- mask width detection: once per CTA ---
    unsigned acc = (unsigned)mask32[2 * f4 + 1] | (unsigned)mask32[2 * (f4 + 128) + 1];
    const int is64 = !__syncthreads_or((int)acc);

    for (int tile = blockIdx.x; tile < N_TILES; tile += GRID) {
        const int mc = tile % M_CHUNKS;
        const int bn = tile / M_CHUNKS;    // 0..127
        const int b  = bn / N;

        // --- gather per-f params for this tile's batch b (L2-resident) ---
        float c1[4], c0[4], p[4], q[4];
        #pragma unroll
        for (int j = 0; j < 4; j++) {
            const int pos = b * F + f4 * 4 + j;
            const int midx = is64 ? mask32[2 * pos] : mask32[pos];
            const float4 e = __ldg(&eta[midx]);
            const float t1 = 2.0f * e.w * LOG2E;   // 2*e3*log2e
            c1[j] = t1;
            c0[j] = -e.z * t1;                     // -2*e2*e3*log2e
            p[j]  = e.x + e.y;                     // e0 + e1
            q[j]  = 2.0f * e.y;                    // 2*e1
        }

        const size_t base = ((size_t)bn * M + (size_t)mc * M_CHUNK) * F4 + f4;

        // --- stream 16 rows: 4 LDG.128 in flight before compute ---
        #pragma unroll
        for (int m = 0; m < M_CHUNK; m += 4) {
            const size_t i0 = base + (size_t)m * F4;
            float4 zv[4];
            zv[0] = __ldcs(&z[i0]);
            zv[1] = __ldcs(&z[i0 + F4]);
            zv[2] = __ldcs(&z[i0 + 2 * F4]);
            zv[3] = __ldcs(&z[i0 + 3 * F4]);

            #pragma unroll
            for (int r = 0; r < 4; r++) {
                float4 o;
                o.x = fmaf(-q[0], rcp_approx(ex2_approx(fmaf(zv[r].x, c1[0], c0[0])) + 1.0f), p[0]);
                o.y = fmaf(-q[1], rcp_approx(ex2_approx(fmaf(zv[r].y, c1[1], c0[1])) + 1.0f), p[1]);
                o.z = fmaf(-q[2], rcp_approx(ex2_approx(fmaf(zv[r].z, c1[2], c0[2])) + 1.0f), p[2]);
                o.w = fmaf(-q[3], rcp_approx(ex2_approx(fmaf(zv[r].w, c1[3], c0[3])) + 1.0f), p[3]);
                __stcs(&out[i0 + (size_t)r * F4], o);
            }
        }
    }
}

extern "C" void kernel_launch(void* const* d_in, const int* in_sizes, int n_in,
                              void* d_out, int out_size) {
    const float4* z      = (const float4*)d_in[0];
    const int*    mask32 = (const int*)d_in[1];      // int32 or int64, detected in-kernel
    const float4* eta    = (const float4*)d_in[2];   // [13,4] fp32
    float4*       out    = (float4*)d_out;

    tanh_rt_kernel<<<GRID, F4>>>(z, mask32, eta, out);
}

// round 6
// speedup vs baseline: 1.0884x; 1.0884x over previous
#include <cuda_runtime.h>
#include <cstdint>

// Problem shape (fixed by reference)
constexpr int B = 16, N = 8, M = 1024, F = 512;
constexpr int F4 = F / 4;              // 128 float4 columns
constexpr int M_CHUNK = 16;            // m-rows per block
constexpr int M_CHUNKS = M / M_CHUNK;  // 64
constexpr float LOG2E = 1.4426950408889634f;

__device__ __forceinline__ float ex2_approx(float x) {
    float r;
    asm("ex2.approx.f32 %0, %1;" : "=f"(r) : "f"(x));
    return r;
}
__device__ __forceinline__ float rcp_approx(float x) {
    float r;
    asm("rcp.approx.f32 %0, %1;" : "=f"(r) : "f"(x));
    return r;
}

// ---------------------------------------------------------------------------
// One block = (b, n, mc); 128 threads = one float4 f-column each. Grid 8192
// (R2 config — persistent/reg-cap/cache-hint variants all measured worse or
// neutral).
//
// R5 addition: software pipelining.
//  (a) The first 2 z rows are prefetched BEFORE the mask->eta param gather,
//      so that ~600-cycle dependent L2 chain overlaps DRAM load latency.
//  (b) The m-loop is rotated: loads for rows m+2,m+3 issue before the
//      compute+store of rows m,m+1 — every warp keeps 32 B/thread in flight
//      during compute instead of draining each iteration.
//
// Mask dtype detection in-block: values in [0,13) => int64 (LE) has every
// odd 32-bit word == 0; OR over 256 odd words nonzero for int32 w.p.
// 1-(1/13)^256.
//
// tanh(x) = 1 - 2/(exp(2x)+1)  ->  out = p - q * rcp(ex2(z*c1 + c0) + 1)
//   c1 = 2*e3*log2e, c0 = -2*e2*e3*log2e, p = e0+e1, q = 2*e1
// ---------------------------------------------------------------------------
__global__ __launch_bounds__(F4, 8)
void tanh_rt_kernel(const float4* __restrict__ z,
                    const int* __restrict__ mask32,
                    const float4* __restrict__ eta,   // [13] of (e0,e1,e2,e3)
                    float4* __restrict__ out) {
    const int f4  = threadIdx.x;           // 0..127
    const int blk = blockIdx.x;
    const int mc  = blk % M_CHUNKS;
    const int bn  = blk / M_CHUNKS;        // 0..B*N-1
    const int b   = bn / N;

    const size_t base = ((size_t)bn * M + (size_t)mc * M_CHUNK) * F4 + f4;

    // --- prefetch rows 0,1 first: overlaps the param-gather chain below ---
    float4 a0 = z[base];
    float4 a1 = z[base + F4];

    // --- in-block mask width detection (block-uniform result) ---
    unsigned acc = (unsigned)mask32[2 * f4 + 1] | (unsigned)mask32[2 * (f4 + 128) + 1];
    const int is64 = !__syncthreads_or((int)acc);

    // --- gather per-f params into registers ---
    float c1[4], c0[4], p[4], q[4];
    #pragma unroll
    for (int j = 0; j < 4; j++) {
        const int pos = b * F + f4 * 4 + j;
        const int midx = is64 ? mask32[2 * pos] : mask32[pos];
        const float4 e = __ldg(&eta[midx]);
        const float t1 = 2.0f * e.w * LOG2E;       // 2*e3*log2e
        c1[j] = t1;
        c0[j] = -e.z * t1;                         // -2*e2*e3*log2e
        p[j]  = e.x + e.y;                         // e0 + e1
        q[j]  = 2.0f * e.y;                        // 2*e1
    }

    // --- rotated loop: load next pair, then compute/store current pair ---
    #pragma unroll
    for (int m = 0; m < M_CHUNK; m += 2) {
        const float4 z0 = a0;
        const float4 z1 = a1;
        if (m + 2 < M_CHUNK) {
            a0 = z[base + (size_t)(m + 2) * F4];
            a1 = z[base + (size_t)(m + 3) * F4];
        }

        float4 o0, o1;
        o0.x = fmaf(-q[0], rcp_approx(ex2_approx(fmaf(z0.x, c1[0], c0[0])) + 1.0f), p[0]);
        o0.y = fmaf(-q[1], rcp_approx(ex2_approx(fmaf(z0.y, c1[1], c0[1])) + 1.0f), p[1]);
        o0.z = fmaf(-q[2], rcp_approx(ex2_approx(fmaf(z0.z, c1[2], c0[2])) + 1.0f), p[2]);
        o0.w = fmaf(-q[3], rcp_approx(ex2_approx(fmaf(z0.w, c1[3], c0[3])) + 1.0f), p[3]);

        o1.x = fmaf(-q[0], rcp_approx(ex2_approx(fmaf(z1.x, c1[0], c0[0])) + 1.0f), p[0]);
        o1.y = fmaf(-q[1], rcp_approx(ex2_approx(fmaf(z1.y, c1[1], c0[1])) + 1.0f), p[1]);
        o1.z = fmaf(-q[2], rcp_approx(ex2_approx(fmaf(z1.z, c1[2], c0[2])) + 1.0f), p[2]);
        o1.w = fmaf(-q[3], rcp_approx(ex2_approx(fmaf(z1.w, c1[3], c0[3])) + 1.0f), p[3]);

        out[base + (size_t)m * F4]       = o0;
        out[base + (size_t)(m + 1) * F4] = o1;
    }
}

extern "C" void kernel_launch(void* const* d_in, const int* in_sizes, int n_in,
                              void* d_out, int out_size) {
    const float4* z      = (const float4*)d_in[0];
    const int*    mask32 = (const int*)d_in[1];      // int32 or int64, detected in-kernel
    const float4* eta    = (const float4*)d_in[2];   // [13,4] fp32
    float4*       out    = (float4*)d_out;

    tanh_rt_kernel<<<B * N * M_CHUNKS, F4>>>(z, mask32, eta, out);
}

// round 7
// speedup vs baseline: 1.0992x; 1.0099x over previous
#include <cuda_runtime.h>
#include <cstdint>

// Problem shape (fixed by reference)
constexpr int B = 16, N = 8, M = 1024, F = 512;
constexpr int F4 = F / 4;              // 128 float4 columns
constexpr int M_CHUNK = 16;            // m-rows per block
constexpr int M_CHUNKS = M / M_CHUNK;  // 64
constexpr float LOG2E = 1.4426950408889634f;

__device__ __forceinline__ float ex2_approx(float x) {
    float r;
    asm("ex2.approx.f32 %0, %1;" : "=f"(r) : "f"(x));
    return r;
}
__device__ __forceinline__ float rcp_approx(float x) {
    float r;
    asm("rcp.approx.f32 %0, %1;" : "=f"(r) : "f"(x));
    return r;
}

// ---------------------------------------------------------------------------
// One block = (b, n, mc); 128 threads = one float4 f-column each. Grid 8192.
//
// R6 confirmed: in-flight load depth during compute is the binding lever
// (rotation depth 2 gave DRAM 77.5->79.7%). R7: rotation depth 4 — 64 B per
// thread in flight during compute. This needs >64 regs, so launch_bounds is
// relaxed to 6 CTAs/SM (reg budget 85); occupancy drop 32->24 warps is
// acceptable per the R3 result (MLP binds, not warp count).
//
// Mask dtype detection in-block: values in [0,13) => int64 (LE) has every
// odd 32-bit word == 0; OR over 256 odd words nonzero for int32 w.p.
// 1-(1/13)^256.
//
// tanh(x) = 1 - 2/(exp(2x)+1)  ->  out = p - q * rcp(ex2(z*c1 + c0) + 1)
//   c1 = 2*e3*log2e, c0 = -2*e2*e3*log2e, p = e0+e1, q = 2*e1
// ---------------------------------------------------------------------------
__global__ __launch_bounds__(F4, 6)
void tanh_rt_kernel(const float4* __restrict__ z,
                    const int* __restrict__ mask32,
                    const float4* __restrict__ eta,   // [13] of (e0,e1,e2,e3)
                    float4* __restrict__ out) {
    const int f4  = threadIdx.x;           // 0..127
    const int blk = blockIdx.x;
    const int mc  = blk % M_CHUNKS;
    const int bn  = blk / M_CHUNKS;        // 0..B*N-1
    const int b   = bn / N;

    const size_t base = ((size_t)bn * M + (size_t)mc * M_CHUNK) * F4 + f4;

    // --- prefetch rows 0..3 first: overlaps the param-gather chain below ---
    float4 a0 = z[base];
    float4 a1 = z[base + F4];
    float4 a2 = z[base + 2 * F4];
    float4 a3 = z[base + 3 * F4];

    // --- in-block mask width detection (block-uniform result) ---
    unsigned acc = (unsigned)mask32[2 * f4 + 1] | (unsigned)mask32[2 * (f4 + 128) + 1];
    const int is64 = !__syncthreads_or((int)acc);

    // --- gather per-f params into registers ---
    float c1[4], c0[4], p[4], q[4];
    #pragma unroll
    for (int j = 0; j < 4; j++) {
        const int pos = b * F + f4 * 4 + j;
        const int midx = is64 ? mask32[2 * pos] : mask32[pos];
        const float4 e = __ldg(&eta[midx]);
        const float t1 = 2.0f * e.w * LOG2E;       // 2*e3*log2e
        c1[j] = t1;
        c0[j] = -e.z * t1;                         // -2*e2*e3*log2e
        p[j]  = e.x + e.y;                         // e0 + e1
        q[j]  = 2.0f * e.y;                        // 2*e1
    }

    // --- rotated loop, depth 4: load rows m+4..m+7 before computing m..m+3 ---
    #pragma unroll
    for (int m = 0; m < M_CHUNK; m += 4) {
        const float4 z0 = a0, z1 = a1, z2 = a2, z3 = a3;
        if (m + 4 < M_CHUNK) {
            a0 = z[base + (size_t)(m + 4) * F4];
            a1 = z[base + (size_t)(m + 5) * F4];
            a2 = z[base + (size_t)(m + 6) * F4];
            a3 = z[base + (size_t)(m + 7) * F4];
        }

        float4 o0, o1, o2, o3;
        o0.x = fmaf(-q[0], rcp_approx(ex2_approx(fmaf(z0.x, c1[0], c0[0])) + 1.0f), p[0]);
        o0.y = fmaf(-q[1], rcp_approx(ex2_approx(fmaf(z0.y, c1[1], c0[1])) + 1.0f), p[1]);
        o0.z = fmaf(-q[2], rcp_approx(ex2_approx(fmaf(z0.z, c1[2], c0[2])) + 1.0f), p[2]);
        o0.w = fmaf(-q[3], rcp_approx(ex2_approx(fmaf(z0.w, c1[3], c0[3])) + 1.0f), p[3]);

        o1.x = fmaf(-q[0], rcp_approx(ex2_approx(fmaf(z1.x, c1[0], c0[0])) + 1.0f), p[0]);
        o1.y = fmaf(-q[1], rcp_approx(ex2_approx(fmaf(z1.y, c1[1], c0[1])) + 1.0f), p[1]);
        o1.z = fmaf(-q[2], rcp_approx(ex2_approx(fmaf(z1.z, c1[2], c0[2])) + 1.0f), p[2]);
        o1.w = fmaf(-q[3], rcp_approx(ex2_approx(fmaf(z1.w, c1[3], c0[3])) + 1.0f), p[3]);

        o2.x = fmaf(-q[0], rcp_approx(ex2_approx(fmaf(z2.x, c1[0], c0[0])) + 1.0f), p[0]);
        o2.y = fmaf(-q[1], rcp_approx(ex2_approx(fmaf(z2.y, c1[1], c0[1])) + 1.0f), p[1]);
        o2.z = fmaf(-q[2], rcp_approx(ex2_approx(fmaf(z2.z, c1[2], c0[2])) + 1.0f), p[2]);
        o2.w = fmaf(-q[3], rcp_approx(ex2_approx(fmaf(z2.w, c1[3], c0[3])) + 1.0f), p[3]);

        o3.x = fmaf(-q[0], rcp_approx(ex2_approx(fmaf(z3.x, c1[0], c0[0])) + 1.0f), p[0]);
        o3.y = fmaf(-q[1], rcp_approx(ex2_approx(fmaf(z3.y, c1[1], c0[1])) + 1.0f), p[1]);
        o3.z = fmaf(-q[2], rcp_approx(ex2_approx(fmaf(z3.z, c1[2], c0[2])) + 1.0f), p[2]);
        o3.w = fmaf(-q[3], rcp_approx(ex2_approx(fmaf(z3.w, c1[3], c0[3])) + 1.0f), p[3]);

        out[base + (size_t)m * F4]       = o0;
        out[base + (size_t)(m + 1) * F4] = o1;
        out[base + (size_t)(m + 2) * F4] = o2;
        out[base + (size_t)(m + 3) * F4] = o3;
    }
}

extern "C" void kernel_launch(void* const* d_in, const int* in_sizes, int n_in,
                              void* d_out, int out_size) {
    const float4* z      = (const float4*)d_in[0];
    const int*    mask32 = (const int*)d_in[1];      // int32 or int64, detected in-kernel
    const float4* eta    = (const float4*)d_in[2];   // [13,4] fp32
    float4*       out    = (float4*)d_out;

    tanh_rt_kernel<<<B * N * M_CHUNKS, F4>>>(z, mask32, eta, out);
}